// round 4
// baseline (speedup 1.0000x reference)
#include <cuda_runtime.h>
#include <math.h>

#define NCH    131072
#define NSTEPS 60
#define HDIM   128

// ---------------------------------------------------------------------------
// Persistent fused EBM Langevin kernel.
// Block: 256 threads (8 warps). Each warp owns a batch of 4 chains and runs
// all 60 MCMC steps on them. Weights w2,w3,w4 live in shared memory with an
// XOR swizzle usable conflict-free in both forward (W) and backward (W^T)
// directions. Per-warp ping-pong activation buffers; only __syncwarp() in the
// hot loop. silu'(a) for layers 1..4 kept in registers for the backward pass.
//
// smem layout (floats):
//   [0      , 16384) w2 swizzled
//   [16384  , 32768) w3 swizzled
//   [32768  , 49152) w4 swizzled
//   [49152  , 57344) per-warp buffers: warp w -> 1024 floats (two 4x128 bufs)
// total = 57344 floats = 229376 bytes (<= 232448 max dynamic smem)
// ---------------------------------------------------------------------------

__device__ __forceinline__ float4 ld4(const float* p) {
    return *reinterpret_cast<const float4*>(p);
}
__device__ __forceinline__ void st4(float* p, float4 v) {
    *reinterpret_cast<float4*>(p) = v;
}

__device__ __forceinline__ void silu_act(float a, float& h, float& sp) {
    float e   = __expf(-a);
    float sig = __fdividef(1.0f, 1.0f + e);
    h  = a * sig;
    sp = sig * (1.0f + a * (1.0f - sig));   // d/da [a*sigmoid(a)]
}

// Forward 128->128 layer: acc_j = b_j + sum_k h_k * W[k][j], then SiLU.
// Ws is the swizzled weight matrix; lane t owns outputs j = 4t..4t+3 for 4 samples.
__device__ __forceinline__ void fwd128(const float* __restrict__ Ws,
                                       const float4 bv,
                                       const float* hin, float* hout,
                                       float sp[4][4], int t)
{
    float acc[4][4];
#pragma unroll
    for (int s = 0; s < 4; s++) {
        acc[s][0] = bv.x; acc[s][1] = bv.y; acc[s][2] = bv.z; acc[s][3] = bv.w;
    }
    const float4* Wv = reinterpret_cast<const float4*>(Ws);
#pragma unroll 2
    for (int k = 0; k < HDIM; k += 4) {
        float4 hv[4];
#pragma unroll
        for (int s = 0; s < 4; s++) hv[s] = ld4(hin + s * HDIM + k);   // broadcast
#pragma unroll
        for (int kk = 0; kk < 4; kk++) {
            const float4 w = Wv[(k + kk) * 32 + (t ^ ((k + kk) & 31))]; // conflict-free
#pragma unroll
            for (int s = 0; s < 4; s++) {
                float h = (&hv[s].x)[kk];
                acc[s][0] = fmaf(h, w.x, acc[s][0]);
                acc[s][1] = fmaf(h, w.y, acc[s][1]);
                acc[s][2] = fmaf(h, w.z, acc[s][2]);
                acc[s][3] = fmaf(h, w.w, acc[s][3]);
            }
        }
    }
#pragma unroll
    for (int s = 0; s < 4; s++) {
        float4 hv;
        silu_act(acc[s][0], hv.x, sp[s][0]);
        silu_act(acc[s][1], hv.y, sp[s][1]);
        silu_act(acc[s][2], hv.z, sp[s][2]);
        silu_act(acc[s][3], hv.w, sp[s][3]);
        st4(hout + s * HDIM + 4 * t, hv);
    }
}

// Backward matmul through W^T: acc[s][i] = sum_j d[s][j] * W[4t+i][j].
// Per-thread column permutation j = jj ^ t + the storage swizzle makes both the
// d-reads and the W-reads bank-conflict-free.
__device__ __forceinline__ void bwdmm(const float* __restrict__ Ws,
                                      const float* din, int t, float acc[4][4])
{
#pragma unroll
    for (int s = 0; s < 4; s++)
#pragma unroll
        for (int i = 0; i < 4; i++) acc[s][i] = 0.0f;

    int rowb[4], swz[4];
#pragma unroll
    for (int i = 0; i < 4; i++) {
        rowb[i] = (4 * t + i) * HDIM;
        swz[i]  = (16 * t + 4 * i) & 127;   // = 4*((4t+i) & 31)
    }
#pragma unroll 4
    for (int jj = 0; jj < HDIM; jj++) {
        int j = jj ^ t;
        float dv[4];
#pragma unroll
        for (int s = 0; s < 4; s++) dv[s] = din[s * HDIM + j];
#pragma unroll
        for (int i = 0; i < 4; i++) {
            float w = Ws[rowb[i] + (j ^ swz[i])];
#pragma unroll
            for (int s = 0; s < 4; s++) acc[s][i] = fmaf(dv[s], w, acc[s][i]);
        }
    }
}

extern "C" __global__ void __launch_bounds__(256, 1)
ebm_langevin_kernel(const float* __restrict__ x0,
                    const float* __restrict__ w1, const float* __restrict__ b1,
                    const float* __restrict__ w2, const float* __restrict__ b2,
                    const float* __restrict__ w3, const float* __restrict__ b3,
                    const float* __restrict__ w4, const float* __restrict__ b4,
                    const float* __restrict__ w5, const float* __restrict__ b5,
                    const float* __restrict__ noise,
                    float* __restrict__ out)
{
    extern __shared__ float smem[];
    float* w2s  = smem;
    float* w3s  = smem + 16384;
    float* w4s  = smem + 32768;
    float* bufs = smem + 49152;

    const int tid = threadIdx.x;

    // Cooperative swizzled weight load: element (k,j) -> k*128 + (j ^ 4*(k&31)).
    // Done at float4 granularity: slot (k,jg) -> (k, jg ^ (k&31)).
    for (int idx = tid; idx < 3 * 4096; idx += 256) {
        int m   = idx >> 12;
        int rem = idx & 4095;
        int k   = rem >> 5;
        int jg  = rem & 31;
        const float* src = (m == 0) ? w2 : (m == 1) ? w3 : w4;
        float*       dst = (m == 0) ? w2s : (m == 1) ? w3s : w4s;
        reinterpret_cast<float4*>(dst)[k * 32 + (jg ^ (k & 31))] =
            reinterpret_cast<const float4*>(src)[rem];
    }
    __syncthreads();

    const int warp = tid >> 5;
    const int t    = tid & 31;
    float* bufA = bufs + warp * 1024;
    float* bufB = bufA + 512;

    const int gw = blockIdx.x * 8 + warp;
    const int nw = gridDim.x * 8;

    // Small weights hoisted to registers (lane t owns columns 4t..4t+3).
    const float4 w1r0 = ld4(w1 + 4 * t);          // w1[0][4t..]
    const float4 w1r1 = ld4(w1 + HDIM + 4 * t);   // w1[1][4t..]
    const float4 b1v  = ld4(b1 + 4 * t);
    const float4 b2v  = ld4(b2 + 4 * t);
    const float4 b3v  = ld4(b3 + 4 * t);
    const float4 b4v  = ld4(b4 + 4 * t);
    const float4 w5v  = ld4(w5 + 4 * t);
    (void)b5; // energy value itself is never needed for the gradient

    for (int b = gw; b < NCH / 4; b += nw) {
        const int base = b * 4;
        float xs[4][2];
#pragma unroll
        for (int s = 0; s < 4; s++) {               // broadcast loads
            xs[s][0] = x0[(base + s) * 2 + 0];
            xs[s][1] = x0[(base + s) * 2 + 1];
        }

        float sp1[4][4], sp2[4][4], sp3[4][4], sp4[4][4];

        for (int step = 0; step < NSTEPS; step++) {
            // ---- forward L1: 2 -> 128 ----
#pragma unroll
            for (int s = 0; s < 4; s++) {
                float4 hv;
                float a;
                a = fmaf(xs[s][0], w1r0.x, fmaf(xs[s][1], w1r1.x, b1v.x));
                silu_act(a, hv.x, sp1[s][0]);
                a = fmaf(xs[s][0], w1r0.y, fmaf(xs[s][1], w1r1.y, b1v.y));
                silu_act(a, hv.y, sp1[s][1]);
                a = fmaf(xs[s][0], w1r0.z, fmaf(xs[s][1], w1r1.z, b1v.z));
                silu_act(a, hv.z, sp1[s][2]);
                a = fmaf(xs[s][0], w1r0.w, fmaf(xs[s][1], w1r1.w, b1v.w));
                silu_act(a, hv.w, sp1[s][3]);
                st4(bufA + s * HDIM + 4 * t, hv);
            }
            __syncwarp();
            fwd128(w2s, b2v, bufA, bufB, sp2, t);   // h1 -> h2
            __syncwarp();
            fwd128(w3s, b3v, bufB, bufA, sp3, t);   // h2 -> h3
            __syncwarp();
            fwd128(w4s, b4v, bufA, bufB, sp4, t);   // h3 -> h4 (h4 unused)
            __syncwarp();

            // ---- backward ----
            // dE/da4 = w5 * silu'(a4)  -> bufA
#pragma unroll
            for (int s = 0; s < 4; s++) {
                float4 dv;
                dv.x = w5v.x * sp4[s][0];
                dv.y = w5v.y * sp4[s][1];
                dv.z = w5v.z * sp4[s][2];
                dv.w = w5v.w * sp4[s][3];
                st4(bufA + s * HDIM + 4 * t, dv);
            }
            __syncwarp();

            float acc[4][4];
            // dE/dh3 = da4 @ W4^T ; da3 = * silu'(a3) -> bufB
            bwdmm(w4s, bufA, t, acc);
#pragma unroll
            for (int s = 0; s < 4; s++) {
                float4 dv;
                dv.x = acc[s][0] * sp3[s][0];
                dv.y = acc[s][1] * sp3[s][1];
                dv.z = acc[s][2] * sp3[s][2];
                dv.w = acc[s][3] * sp3[s][3];
                st4(bufB + s * HDIM + 4 * t, dv);
            }
            __syncwarp();
            // dE/dh2 = da3 @ W3^T ; da2 = * silu'(a2) -> bufA
            bwdmm(w3s, bufB, t, acc);
#pragma unroll
            for (int s = 0; s < 4; s++) {
                float4 dv;
                dv.x = acc[s][0] * sp2[s][0];
                dv.y = acc[s][1] * sp2[s][1];
                dv.z = acc[s][2] * sp2[s][2];
                dv.w = acc[s][3] * sp2[s][3];
                st4(bufA + s * HDIM + 4 * t, dv);
            }
            __syncwarp();
            // dE/dh1 = da2 @ W2^T ; da1 = * silu'(a1) ; dx = da1 @ W1^T
            bwdmm(w2s, bufA, t, acc);

            float pdx[4][2];
#pragma unroll
            for (int s = 0; s < 4; s++) {
                float d0 = acc[s][0] * sp1[s][0];
                float d1 = acc[s][1] * sp1[s][1];
                float d2 = acc[s][2] * sp1[s][2];
                float d3 = acc[s][3] * sp1[s][3];
                pdx[s][0] = fmaf(d0, w1r0.x, fmaf(d1, w1r0.y,
                            fmaf(d2, w1r0.z, d3 * w1r0.w)));
                pdx[s][1] = fmaf(d0, w1r1.x, fmaf(d1, w1r1.y,
                            fmaf(d2, w1r1.z, d3 * w1r1.w)));
            }
            // butterfly reduce across the warp -> every lane holds full dx
#pragma unroll
            for (int off = 16; off > 0; off >>= 1) {
#pragma unroll
                for (int s = 0; s < 4; s++) {
                    pdx[s][0] += __shfl_xor_sync(0xffffffffu, pdx[s][0], off);
                    pdx[s][1] += __shfl_xor_sync(0xffffffffu, pdx[s][1], off);
                }
            }

            // ---- Langevin update (replicated identically in all lanes) ----
            float fi  = (float)step;
            float eps = 10.0f * (1.0f - fi / 60.0f);
            float sq  = sqrtf(2.0f * eps);
#pragma unroll
            for (int s = 0; s < 4; s++) {
#pragma unroll
                for (int c = 0; c < 2; c++) {
                    float nz = noise[((size_t)step * NCH + base + s) * 2 + c];
                    float g  = fminf(fmaxf(pdx[s][c], -0.03f), 0.03f);
                    float xv = xs[s][c] + sq * nz * 0.005f + eps * g;
                    xs[s][c] = fminf(fmaxf(xv, -2.43f), 3.05f);
                }
            }
            __syncwarp();   // bufA reusable next step
        }

        if (t < 8) {
            int s = t >> 1, c = t & 1;
            out[(base + s) * 2 + c] = xs[s][c];
        }
    }
}

extern "C" void kernel_launch(void* const* d_in, const int* in_sizes, int n_in,
                              void* d_out, int out_size)
{
    const float* x0    = (const float*)d_in[0];
    const float* w1    = (const float*)d_in[1];
    const float* b1    = (const float*)d_in[2];
    const float* w2    = (const float*)d_in[3];
    const float* b2    = (const float*)d_in[4];
    const float* w3    = (const float*)d_in[5];
    const float* b3    = (const float*)d_in[6];
    const float* w4    = (const float*)d_in[7];
    const float* b4    = (const float*)d_in[8];
    const float* w5    = (const float*)d_in[9];
    const float* b5    = (const float*)d_in[10];
    const float* noise = (const float*)d_in[11];

    const int smemBytes = 57344 * (int)sizeof(float);   // 229376
    cudaFuncSetAttribute(ebm_langevin_kernel,
                         cudaFuncAttributeMaxDynamicSharedMemorySize, smemBytes);

    int nsm = 148;
    cudaDeviceGetAttribute(&nsm, cudaDevAttrMultiProcessorCount, 0);

    ebm_langevin_kernel<<<nsm, 256, smemBytes>>>(
        x0, w1, b1, w2, b2, w3, b3, w4, b4, w5, b5, noise, (float*)d_out);
}

// round 5
// speedup vs baseline: 1.4809x; 1.4809x over previous
#include <cuda_runtime.h>
#include <math.h>

#define NCH    131072
#define NSTEPS 60
#define HDIM   128

typedef unsigned long long ull;

// ---------------------------------------------------------------------------
// Packed fp32x2 helpers (sm_103a FFMA2 — only reachable via PTX f32x2 ops).
// ---------------------------------------------------------------------------
__device__ __forceinline__ ull pack2(float lo, float hi) {
    ull r; asm("mov.b64 %0, {%1, %2};" : "=l"(r) : "f"(lo), "f"(hi)); return r;
}
__device__ __forceinline__ void unpack2(ull v, float& lo, float& hi) {
    asm("mov.b64 {%0, %1}, %2;" : "=f"(lo), "=f"(hi) : "l"(v));
}
__device__ __forceinline__ void fma2(ull& c, ull a, ull b) {
    asm("fma.rn.f32x2 %0, %1, %2, %0;" : "+l"(c) : "l"(a), "l"(b));
}

__device__ __forceinline__ float4 ld4(const float* p) {
    return *reinterpret_cast<const float4*>(p);
}
__device__ __forceinline__ void st4(float* p, float4 v) {
    *reinterpret_cast<float4*>(p) = v;
}

__device__ __forceinline__ void silu_act(float a, float& h, float& sp) {
    float e   = __expf(-a);
    float sig = __fdividef(1.0f, 1.0f + e);
    h  = a * sig;
    sp = sig * (1.0f + a * (1.0f - sig));
}

// ---------------------------------------------------------------------------
// Duplicated-activation buffer (per warp, 4 KB):
//   element (k, s) holds pair (h,h). Row = k>>2 (128 B), 16B-slot within row:
//   (2*(k&3) + (s>>1)) ^ ((k>>2)&7), low/high 8 B = s even/odd.
// Writers (lane t owns k = 4t+i, so k>>2 == t) are conflict-free via the
// (t&7) XOR; readers are pure broadcasts with compile-time offsets.
// ---------------------------------------------------------------------------
__device__ __forceinline__ void dup_store(char* dup, int t, const float hv[4][4]) {
    char* bt = dup + t * 128;
    const int t7 = t & 7;
#pragma unroll
    for (int i = 0; i < 4; i++) {
#pragma unroll
        for (int sp = 0; sp < 2; sp++) {
            char* p = bt + ((((2 * i + sp) ^ t7)) << 4);
            *(ull*)(p)     = pack2(hv[i][2 * sp],     hv[i][2 * sp]);
            *(ull*)(p + 8) = pack2(hv[i][2 * sp + 1], hv[i][2 * sp + 1]);
        }
    }
}

// ---------------------------------------------------------------------------
// Forward 128->128 layer, packed over output-pairs.
// Weight quad q of row k lives at 16B-slot (q ^ ((k>>2)&7)); lane t reads its
// own quad t with one LOP3 per k. Activations arrive as broadcast (h,h) pairs.
// Accumulation order over k is ascending (bit-identical to scalar version).
// ---------------------------------------------------------------------------
template<bool STORE_H>
__device__ __forceinline__ void fwd128p(const char* __restrict__ Ws,
                                        char* dup, float4 bv,
                                        float sp[4][4], int t)
{
    const ull bp0 = pack2(bv.x, bv.y), bp1 = pack2(bv.z, bv.w);
    ull a01[4], a23[4];
#pragma unroll
    for (int s = 0; s < 4; s++) { a01[s] = bp0; a23[s] = bp1; }

    const int t16 = t << 4;
#pragma unroll 1
    for (int k0 = 0; k0 < HDIM; k0 += 32) {   // k0 multiple of 32 => (k>>2)&7 == (j>>2)&7
        const char* wb = Ws  + k0 * 512;
        const char* db = dup + k0 * 32;
#pragma unroll
        for (int j = 0; j < 32; j++) {
            const int c  = (j >> 2) & 7;
            const int cc = c << 4;
            ulonglong2 w = *(const ulonglong2*)(wb + j * 512 + (t16 ^ cc));
            const char* dr = db + ((j >> 2) << 7);
            ulonglong2 h01 = *(const ulonglong2*)(dr + (((2 * (j & 3) + 0) ^ c) << 4));
            ulonglong2 h23 = *(const ulonglong2*)(dr + (((2 * (j & 3) + 1) ^ c) << 4));
            fma2(a01[0], h01.x, w.x); fma2(a23[0], h01.x, w.y);
            fma2(a01[1], h01.y, w.x); fma2(a23[1], h01.y, w.y);
            fma2(a01[2], h23.x, w.x); fma2(a23[2], h23.x, w.y);
            fma2(a01[3], h23.y, w.x); fma2(a23[3], h23.y, w.y);
        }
    }
    __syncwarp();   // all lanes done reading dup before (possible) overwrite

    float hv[4][4];  // [i][s]
#pragma unroll
    for (int s = 0; s < 4; s++) {
        float o0, o1, o2, o3;
        unpack2(a01[s], o0, o1); unpack2(a23[s], o2, o3);
        silu_act(o0, hv[0][s], sp[s][0]);
        silu_act(o1, hv[1][s], sp[s][1]);
        silu_act(o2, hv[2][s], sp[s][2]);
        silu_act(o3, hv[3][s], sp[s][3]);
    }
    if (STORE_H) {
        dup_store(dup, t, hv);
        __syncwarp();
    }
}

// ---------------------------------------------------------------------------
// Backward through W^T: accf[s][i] = sum_j d[s][j] * W[4t+i][j].
// Lane t reads rows 4t+i as swizzled float4 (slot q ^ (t&7), conflict-free);
// d is read as broadcast float4 with immediate offsets. Packed over even/odd j,
// horizontal add at the end. Trailing __syncwarp so caller may overwrite dbuf.
// ---------------------------------------------------------------------------
__device__ __forceinline__ void bwd128p(const char* __restrict__ Ws,
                                        const char* dbuf, int t, float accf[4][4])
{
    ull acc[4][4];
    const ull z = pack2(0.0f, 0.0f);
#pragma unroll
    for (int s = 0; s < 4; s++)
#pragma unroll
        for (int i = 0; i < 4; i++) acc[s][i] = z;

    const char* wr0 = Ws + (4 * t + 0) * 512;
    const char* wr1 = Ws + (4 * t + 1) * 512;
    const char* wr2 = Ws + (4 * t + 2) * 512;
    const char* wr3 = Ws + (4 * t + 3) * 512;
    const int t7x = (t & 7) << 4;

#pragma unroll 1
    for (int q0 = 0; q0 < 32; q0 += 8) {      // q0 multiple of 8: 16q0 | (t7x ^ 16jq)
        const char* db = dbuf + q0 * 16;
        const int   qb = q0 << 4;
#pragma unroll
        for (int jq = 0; jq < 8; jq++) {
            const int off = qb + (t7x ^ (jq << 4));
            ulonglong2 w0 = *(const ulonglong2*)(wr0 + off);
            ulonglong2 w1 = *(const ulonglong2*)(wr1 + off);
            ulonglong2 w2 = *(const ulonglong2*)(wr2 + off);
            ulonglong2 w3 = *(const ulonglong2*)(wr3 + off);
#pragma unroll
            for (int s = 0; s < 4; s++) {
                ulonglong2 dv = *(const ulonglong2*)(db + s * 512 + jq * 16);
                fma2(acc[s][0], dv.x, w0.x); fma2(acc[s][0], dv.y, w0.y);
                fma2(acc[s][1], dv.x, w1.x); fma2(acc[s][1], dv.y, w1.y);
                fma2(acc[s][2], dv.x, w2.x); fma2(acc[s][2], dv.y, w2.y);
                fma2(acc[s][3], dv.x, w3.x); fma2(acc[s][3], dv.y, w3.y);
            }
        }
    }
    __syncwarp();   // all lanes done reading dbuf

#pragma unroll
    for (int s = 0; s < 4; s++)
#pragma unroll
        for (int i = 0; i < 4; i++) {
            float lo, hi; unpack2(acc[s][i], lo, hi);
            accf[s][i] = lo + hi;
        }
}

// ---------------------------------------------------------------------------
// smem: w2s/w3s/w4s swizzled fp32 (3 x 64 KB) + 8 warps x 4 KB buffers
//       = 229376 B total.
// ---------------------------------------------------------------------------
extern "C" __global__ void __launch_bounds__(256, 1)
ebm_langevin_kernel(const float* __restrict__ x0,
                    const float* __restrict__ w1, const float* __restrict__ b1,
                    const float* __restrict__ w2, const float* __restrict__ b2,
                    const float* __restrict__ w3, const float* __restrict__ b3,
                    const float* __restrict__ w4, const float* __restrict__ b4,
                    const float* __restrict__ w5, const float* __restrict__ b5,
                    const float* __restrict__ noise,
                    float* __restrict__ out)
{
    extern __shared__ float smem[];
    float* w2s = smem;
    float* w3s = smem + 16384;
    float* w4s = smem + 32768;
    char*  bufs = (char*)(smem + 49152);

    const int tid = threadIdx.x;

    // Cooperative swizzled weight load: quad q of row k -> slot q ^ ((k>>2)&7).
    for (int idx = tid; idx < 3 * 4096; idx += 256) {
        int m   = idx >> 12;
        int rem = idx & 4095;
        int k   = rem >> 5;
        int q   = rem & 31;
        const float* src = (m == 0) ? w2 : (m == 1) ? w3 : w4;
        float*       dst = (m == 0) ? w2s : (m == 1) ? w3s : w4s;
        reinterpret_cast<float4*>(dst)[k * 32 + (q ^ ((k >> 2) & 7))] =
            reinterpret_cast<const float4*>(src)[rem];
    }
    __syncthreads();

    const int warp = tid >> 5;
    const int t    = tid & 31;
    char*  dup  = bufs + warp * 4096;        // duplicated-h buffer (fwd)
    float* dbuf = (float*)dup;               // plain d buffer (bwd), aliased

    const char* w2c = (const char*)w2s;
    const char* w3c = (const char*)w3s;
    const char* w4c = (const char*)w4s;

    const int gw = blockIdx.x * 8 + warp;
    const int nw = gridDim.x * 8;

    const float4 w1r0 = ld4(w1 + 4 * t);
    const float4 w1r1 = ld4(w1 + HDIM + 4 * t);
    const float4 b1v  = ld4(b1 + 4 * t);
    const float4 b2v  = ld4(b2 + 4 * t);
    const float4 b3v  = ld4(b3 + 4 * t);
    const float4 b4v  = ld4(b4 + 4 * t);
    const float4 w5v  = ld4(w5 + 4 * t);
    (void)b5;

    for (int b = gw; b < NCH / 4; b += nw) {
        const int base = b * 4;
        float xs[4][2];
#pragma unroll
        for (int s = 0; s < 4; s++) {
            xs[s][0] = x0[(base + s) * 2 + 0];
            xs[s][1] = x0[(base + s) * 2 + 1];
        }

        float sp1[4][4], sp2[4][4], sp3[4][4], sp4[4][4];

        for (int step = 0; step < NSTEPS; step++) {
            // ---- forward L1: 2 -> 128 ----
            {
                float hv[4][4];   // [i][s]
#pragma unroll
                for (int s = 0; s < 4; s++) {
                    float a;
                    a = fmaf(xs[s][0], w1r0.x, fmaf(xs[s][1], w1r1.x, b1v.x));
                    silu_act(a, hv[0][s], sp1[s][0]);
                    a = fmaf(xs[s][0], w1r0.y, fmaf(xs[s][1], w1r1.y, b1v.y));
                    silu_act(a, hv[1][s], sp1[s][1]);
                    a = fmaf(xs[s][0], w1r0.z, fmaf(xs[s][1], w1r1.z, b1v.z));
                    silu_act(a, hv[2][s], sp1[s][2]);
                    a = fmaf(xs[s][0], w1r0.w, fmaf(xs[s][1], w1r1.w, b1v.w));
                    silu_act(a, hv[3][s], sp1[s][3]);
                }
                dup_store(dup, t, hv);
                __syncwarp();
            }

            fwd128p<true >(w2c, dup, b2v, sp2, t);   // h1 -> h2
            fwd128p<true >(w3c, dup, b3v, sp3, t);   // h2 -> h3
            fwd128p<false>(w4c, dup, b4v, sp4, t);   // h3 -> (sp4 only)

            // ---- backward seed: d_a4 = w5 * silu'(a4) ----
#pragma unroll
            for (int s = 0; s < 4; s++) {
                float4 dv;
                dv.x = w5v.x * sp4[s][0];
                dv.y = w5v.y * sp4[s][1];
                dv.z = w5v.z * sp4[s][2];
                dv.w = w5v.w * sp4[s][3];
                st4(dbuf + s * HDIM + 4 * t, dv);
            }
            __syncwarp();

            float accf[4][4];
            // d_a3 = (d_a4 @ W4^T) * silu'(a3)
            bwd128p(w4c, (const char*)dbuf, t, accf);
#pragma unroll
            for (int s = 0; s < 4; s++) {
                float4 dv;
                dv.x = accf[s][0] * sp3[s][0];
                dv.y = accf[s][1] * sp3[s][1];
                dv.z = accf[s][2] * sp3[s][2];
                dv.w = accf[s][3] * sp3[s][3];
                st4(dbuf + s * HDIM + 4 * t, dv);
            }
            __syncwarp();
            // d_a2 = (d_a3 @ W3^T) * silu'(a2)
            bwd128p(w3c, (const char*)dbuf, t, accf);
#pragma unroll
            for (int s = 0; s < 4; s++) {
                float4 dv;
                dv.x = accf[s][0] * sp2[s][0];
                dv.y = accf[s][1] * sp2[s][1];
                dv.z = accf[s][2] * sp2[s][2];
                dv.w = accf[s][3] * sp2[s][3];
                st4(dbuf + s * HDIM + 4 * t, dv);
            }
            __syncwarp();
            // d_a1 = (d_a2 @ W2^T) * silu'(a1) ; dx = d_a1 @ W1^T
            bwd128p(w2c, (const char*)dbuf, t, accf);

            float pdx[4][2];
#pragma unroll
            for (int s = 0; s < 4; s++) {
                float d0 = accf[s][0] * sp1[s][0];
                float d1 = accf[s][1] * sp1[s][1];
                float d2 = accf[s][2] * sp1[s][2];
                float d3 = accf[s][3] * sp1[s][3];
                pdx[s][0] = fmaf(d0, w1r0.x, fmaf(d1, w1r0.y,
                            fmaf(d2, w1r0.z, d3 * w1r0.w)));
                pdx[s][1] = fmaf(d0, w1r1.x, fmaf(d1, w1r1.y,
                            fmaf(d2, w1r1.z, d3 * w1r1.w)));
            }
#pragma unroll
            for (int off = 16; off > 0; off >>= 1) {
#pragma unroll
                for (int s = 0; s < 4; s++) {
                    pdx[s][0] += __shfl_xor_sync(0xffffffffu, pdx[s][0], off);
                    pdx[s][1] += __shfl_xor_sync(0xffffffffu, pdx[s][1], off);
                }
            }

            // ---- Langevin update (replicated identically in all lanes) ----
            float fi  = (float)step;
            float eps = 10.0f * (1.0f - fi / 60.0f);
            float sq  = sqrtf(2.0f * eps);
#pragma unroll
            for (int s = 0; s < 4; s++) {
#pragma unroll
                for (int c = 0; c < 2; c++) {
                    float nz = noise[((size_t)step * NCH + base + s) * 2 + c];
                    float g  = fminf(fmaxf(pdx[s][c], -0.03f), 0.03f);
                    float xv = xs[s][c] + sq * nz * 0.005f + eps * g;
                    xs[s][c] = fminf(fmaxf(xv, -2.43f), 3.05f);
                }
            }
            // next L1 dup_store is safe: bwd128p already syncwarp'd after reads
        }

        if (t < 8) {
            int s = t >> 1, c = t & 1;
            out[(base + s) * 2 + c] = xs[s][c];
        }
    }
}

extern "C" void kernel_launch(void* const* d_in, const int* in_sizes, int n_in,
                              void* d_out, int out_size)
{
    const float* x0    = (const float*)d_in[0];
    const float* w1    = (const float*)d_in[1];
    const float* b1    = (const float*)d_in[2];
    const float* w2    = (const float*)d_in[3];
    const float* b2    = (const float*)d_in[4];
    const float* w3    = (const float*)d_in[5];
    const float* b3    = (const float*)d_in[6];
    const float* w4    = (const float*)d_in[7];
    const float* b4    = (const float*)d_in[8];
    const float* w5    = (const float*)d_in[9];
    const float* b5    = (const float*)d_in[10];
    const float* noise = (const float*)d_in[11];

    const int smemBytes = 57344 * (int)sizeof(float);   // 229376
    cudaFuncSetAttribute(ebm_langevin_kernel,
                         cudaFuncAttributeMaxDynamicSharedMemorySize, smemBytes);

    int nsm = 148;
    cudaDeviceGetAttribute(&nsm, cudaDevAttrMultiProcessorCount, 0);

    ebm_langevin_kernel<<<nsm, 256, smemBytes>>>(
        x0, w1, b1, w2, b2, w3, b3, w4, b4, w5, b5, noise, (float*)d_out);
}

// round 7
// speedup vs baseline: 1.7697x; 1.1950x over previous
#include <cuda_runtime.h>
#include <math.h>

#define NCH    131072
#define NSTEPS 60
#define HDIM   128

typedef unsigned long long ull;

// ---------------------------------------------------------------------------
// Packed fp32x2 helpers (sm_103a FFMA2 — only reachable via PTX f32x2 ops).
// ---------------------------------------------------------------------------
static __device__ __forceinline__ ull pack2(float lo, float hi) {
    ull r; asm("mov.b64 %0, {%1, %2};" : "=l"(r) : "f"(lo), "f"(hi)); return r;
}
static __device__ __forceinline__ void unpack2(ull v, float& lo, float& hi) {
    asm("mov.b64 {%0, %1}, %2;" : "=f"(lo), "=f"(hi) : "l"(v));
}
static __device__ __forceinline__ void fma2(ull& c, ull a, ull b) {
    asm("fma.rn.f32x2 %0, %1, %2, %0;" : "+l"(c) : "l"(a), "l"(b));
}

static __device__ __forceinline__ float4 ld4(const float* p) {
    return *reinterpret_cast<const float4*>(p);
}
static __device__ __forceinline__ void st4(float* p, float4 v) {
    *reinterpret_cast<float4*>(p) = v;
}

static __device__ __forceinline__ void silu_act(float a, float& h, float& sp) {
    float e   = __expf(-a);
    float sig = __fdividef(1.0f, 1.0f + e);
    h  = a * sig;
    sp = sig * (1.0f + a * (1.0f - sig));
}
static __device__ __forceinline__ float silu_prime(float a) {
    float e   = __expf(-a);
    float sig = __fdividef(1.0f, 1.0f + e);
    return sig * (1.0f + a * (1.0f - sig));
}

// ---------------------------------------------------------------------------
// Per-warp 4 KB buffer, aliased between phases.
//
// Forward activations (pair-major, swizzled 16B slots, NO duplication):
//   slot(k, half) = (2k + half) ^ ((k>>2)&7)   (byte addr = slot*16)
//   half 0 holds f32x2 pairs (s0,s1),(s2,s3); half 1 holds (s4,s5),(s6,s7).
//   Writers: lane t owns k = 4t+i -> bank (2i+half)^(t&7): conflict-free ST.128.
//   Readers: 2x LDS.128 broadcast per k with compile-time offsets.
//
// Backward d-buffer (plain sample-major): d[s][j] at s*512 + 4j bytes.
//
// Weights (shared, 3 x 64 KB): quad q of row k at 16B slot q ^ ((k>>2)&7).
//   fwd reads quad t of row k (distinct -> conflict-free);
//   bwd reads rows 4t+i quad-wise (distinct -> conflict-free).
// ---------------------------------------------------------------------------

// Forward 128->128, 8 samples, sample-pair-packed FMA2; weights duplicated
// (w,w) via register packs. sp (silu') kept in fp32: sp[i*8 + s], s=0..7.
// SEED=true (layer 4): skip h store; write d_a4 = w5 (.) silu'(a4) into dbuf.
template<bool SEED>
static __device__ __forceinline__ void fwd8(const char* __restrict__ Ws,
                                            char* __restrict__ ab,
                                            float4 bv, float* __restrict__ sp,
                                            int t, const int* stofs,
                                            float4 w5v, float* __restrict__ dbuf)
{
    ull acc[4][4];
    {
        ull bd0 = pack2(bv.x, bv.x), bd1 = pack2(bv.y, bv.y);
        ull bd2 = pack2(bv.z, bv.z), bd3 = pack2(bv.w, bv.w);
#pragma unroll
        for (int p = 0; p < 4; p++) {
            acc[p][0] = bd0; acc[p][1] = bd1; acc[p][2] = bd2; acc[p][3] = bd3;
        }
    }
    const int t16 = t << 4;
#pragma unroll 1
    for (int k0 = 0; k0 < HDIM; k0 += 32) {   // swizzle period
        const char* wb = Ws + k0 * 512;
        const char* hb = ab + k0 * 32;
#pragma unroll
        for (int kk = 0; kk < 32; kk++) {
            const int c = (kk >> 2) & 7;      // compile-time
            float4 w = *(const float4*)(wb + kk * 512 + (t16 ^ (c << 4)));
            ull wd0 = pack2(w.x, w.x), wd1 = pack2(w.y, w.y);
            ull wd2 = pack2(w.z, w.z), wd3 = pack2(w.w, w.w);
            ulonglong2 hA = *(const ulonglong2*)(hb + (((2*kk    ) ^ c) << 4));
            ulonglong2 hB = *(const ulonglong2*)(hb + (((2*kk + 1) ^ c) << 4));
            fma2(acc[0][0], hA.x, wd0); fma2(acc[0][1], hA.x, wd1);
            fma2(acc[0][2], hA.x, wd2); fma2(acc[0][3], hA.x, wd3);
            fma2(acc[1][0], hA.y, wd0); fma2(acc[1][1], hA.y, wd1);
            fma2(acc[1][2], hA.y, wd2); fma2(acc[1][3], hA.y, wd3);
            fma2(acc[2][0], hB.x, wd0); fma2(acc[2][1], hB.x, wd1);
            fma2(acc[2][2], hB.x, wd2); fma2(acc[2][3], hB.x, wd3);
            fma2(acc[3][0], hB.y, wd0); fma2(acc[3][1], hB.y, wd1);
            fma2(acc[3][2], hB.y, wd2); fma2(acc[3][3], hB.y, wd3);
        }
    }
    __syncwarp();   // everyone done reading ab (may be overwritten below)

    if (!SEED) {
        ull hp[4][4];
#pragma unroll
        for (int p = 0; p < 4; p++)
#pragma unroll
            for (int i = 0; i < 4; i++) {
                float a0, a1; unpack2(acc[p][i], a0, a1);
                float h0, s0, h1, s1;
                silu_act(a0, h0, s0);
                silu_act(a1, h1, s1);
                sp[i * 8 + 2 * p]     = s0;
                sp[i * 8 + 2 * p + 1] = s1;
                hp[p][i] = pack2(h0, h1);
            }
#pragma unroll
        for (int i = 0; i < 4; i++) {
            *(ulonglong2*)(ab + stofs[2*i+0]) = make_ulonglong2(hp[0][i], hp[1][i]);
            *(ulonglong2*)(ab + stofs[2*i+1]) = make_ulonglong2(hp[2][i], hp[3][i]);
        }
        __syncwarp();
    } else {
        // d_a4 = w5 (.) silu'(a4), stored sample-major; sp4 never materialized.
        float w5a[4] = {w5v.x, w5v.y, w5v.z, w5v.w};
#pragma unroll
        for (int p = 0; p < 4; p++) {
            float d0[4], d1[4];
#pragma unroll
            for (int i = 0; i < 4; i++) {
                float a0, a1; unpack2(acc[p][i], a0, a1);
                d0[i] = w5a[i] * silu_prime(a0);
                d1[i] = w5a[i] * silu_prime(a1);
            }
            st4(dbuf + (2*p    ) * HDIM + 4 * t, make_float4(d0[0], d0[1], d0[2], d0[3]));
            st4(dbuf + (2*p + 1) * HDIM + 4 * t, make_float4(d1[0], d1[1], d1[2], d1[3]));
        }
        __syncwarp();
    }
}

// Backward through W^T, 8 samples, j-packed (even/odd j in the f32x2 lanes).
// accf[s][i] = sum_j d[s][j] * W[4t+i][j].
static __device__ __forceinline__ void bwd8(const char* __restrict__ Ws,
                                            const char* __restrict__ db,
                                            int t, int t7, float accf[8][4])
{
    ull acc[8][4];
    const ull z = pack2(0.0f, 0.0f);
#pragma unroll
    for (int s = 0; s < 8; s++)
#pragma unroll
        for (int i = 0; i < 4; i++) acc[s][i] = z;

    const char* wr0 = Ws + (4 * t + 0) * 512;
    const char* wr1 = Ws + (4 * t + 1) * 512;
    const char* wr2 = Ws + (4 * t + 2) * 512;
    const char* wr3 = Ws + (4 * t + 3) * 512;

#pragma unroll 1
    for (int qi = 0; qi < 8; qi++) {          // q = 8g + qi covers all 32 quads
        const int wo   = (qi ^ t7) << 4;
        const int dofs = qi << 4;
#pragma unroll
        for (int g = 0; g < 4; g++) {
            const int go = g * 128;
            ulonglong2 w0 = *(const ulonglong2*)(wr0 + go + wo);
            ulonglong2 w1 = *(const ulonglong2*)(wr1 + go + wo);
            ulonglong2 w2 = *(const ulonglong2*)(wr2 + go + wo);
            ulonglong2 w3 = *(const ulonglong2*)(wr3 + go + wo);
#pragma unroll
            for (int s = 0; s < 8; s++) {
                ulonglong2 dv = *(const ulonglong2*)(db + s * 512 + go + dofs);
                fma2(acc[s][0], dv.x, w0.x); fma2(acc[s][0], dv.y, w0.y);
                fma2(acc[s][1], dv.x, w1.x); fma2(acc[s][1], dv.y, w1.y);
                fma2(acc[s][2], dv.x, w2.x); fma2(acc[s][2], dv.y, w2.y);
                fma2(acc[s][3], dv.x, w3.x); fma2(acc[s][3], dv.y, w3.y);
            }
        }
    }
    __syncwarp();   // everyone done reading db

#pragma unroll
    for (int s = 0; s < 8; s++)
#pragma unroll
        for (int i = 0; i < 4; i++) {
            float lo, hi; unpack2(acc[s][i], lo, hi);
            accf[s][i] = lo + hi;
        }
}

// smem: 3 x 64KB swizzled weights + 8 warps x 4KB buffers = 229376 B
extern "C" __global__ void __launch_bounds__(256, 1)
ebm_langevin_kernel(const float* __restrict__ x0,
                    const float* __restrict__ w1, const float* __restrict__ b1,
                    const float* __restrict__ w2, const float* __restrict__ b2,
                    const float* __restrict__ w3, const float* __restrict__ b3,
                    const float* __restrict__ w4, const float* __restrict__ b4,
                    const float* __restrict__ w5, const float* __restrict__ b5,
                    const float* __restrict__ noise,
                    float* __restrict__ out)
{
    extern __shared__ float smem[];
    float* w2s = smem;
    float* w3s = smem + 16384;
    float* w4s = smem + 32768;
    char*  bufs = (char*)(smem + 49152);

    const int tid = threadIdx.x;

    // Cooperative swizzled weight load: quad q of row k -> slot q ^ ((k>>2)&7).
    for (int idx = tid; idx < 3 * 4096; idx += 256) {
        int m   = idx >> 12;
        int rem = idx & 4095;
        int k   = rem >> 5;
        int q   = rem & 31;
        const float* src = (m == 0) ? w2 : (m == 1) ? w3 : w4;
        float*       dst = (m == 0) ? w2s : (m == 1) ? w3s : w4s;
        reinterpret_cast<float4*>(dst)[k * 32 + (q ^ ((k >> 2) & 7))] =
            reinterpret_cast<const float4*>(src)[rem];
    }
    __syncthreads();

    const int warp = tid >> 5;
    const int t    = tid & 31;
    const int t7   = t & 7;
    char*  ab   = bufs + warp * 4096;
    float* dbuf = (float*)ab;

    const char* w2c = (const char*)w2s;
    const char* w3c = (const char*)w3s;
    const char* w4c = (const char*)w4s;

    // Per-lane activation-store offsets (conflict-free swizzled ST.128):
    // k = 4t+i, half -> byte ((8t + 2i + half) ^ (t&7)) * 16
    int stofs[8];
#pragma unroll
    for (int i = 0; i < 4; i++)
#pragma unroll
        for (int half = 0; half < 2; half++)
            stofs[2 * i + half] = (t << 7) + ((((i << 1) | half) ^ t7) << 4);

    const int gw = blockIdx.x * 8 + warp;
    const int nw = gridDim.x * 8;

    const float4 w1r0 = ld4(w1 + 4 * t);
    const float4 w1r1 = ld4(w1 + HDIM + 4 * t);
    const float4 b1v  = ld4(b1 + 4 * t);
    const float4 b2v  = ld4(b2 + 4 * t);
    const float4 b3v  = ld4(b3 + 4 * t);
    const float4 b4v  = ld4(b4 + 4 * t);
    const float4 w5v  = ld4(w5 + 4 * t);
    (void)b5;
    float w1A[4] = {w1r0.x, w1r0.y, w1r0.z, w1r0.w};
    float w1B[4] = {w1r1.x, w1r1.y, w1r1.z, w1r1.w};
    float bb1[4] = {b1v.x,  b1v.y,  b1v.z,  b1v.w};

    for (int b = gw; b < NCH / 8; b += nw) {
        const int base = b * 8;
        float xs[8][2];
#pragma unroll
        for (int s = 0; s < 8; s++) {
            xs[s][0] = x0[(base + s) * 2 + 0];
            xs[s][1] = x0[(base + s) * 2 + 1];
        }

        // fp32 silu' caches: sp[i*8 + s], i = output quad-lane, s = sample.
        float sp1[32], sp2[32], sp3[32];

        for (int step = 0; step < NSTEPS; step++) {
            // ---- forward L1: 2 -> 128 (writes pair-major activation buf) ----
            {
                ull hp[4][4];
#pragma unroll
                for (int p = 0; p < 4; p++)
#pragma unroll
                    for (int i = 0; i < 4; i++) {
                        float a0 = fmaf(xs[2*p  ][0], w1A[i],
                                   fmaf(xs[2*p  ][1], w1B[i], bb1[i]));
                        float a1 = fmaf(xs[2*p+1][0], w1A[i],
                                   fmaf(xs[2*p+1][1], w1B[i], bb1[i]));
                        float h0, s0, h1, s1;
                        silu_act(a0, h0, s0);
                        silu_act(a1, h1, s1);
                        sp1[i * 8 + 2 * p]     = s0;
                        sp1[i * 8 + 2 * p + 1] = s1;
                        hp[p][i] = pack2(h0, h1);
                    }
#pragma unroll
                for (int i = 0; i < 4; i++) {
                    *(ulonglong2*)(ab + stofs[2*i+0]) = make_ulonglong2(hp[0][i], hp[1][i]);
                    *(ulonglong2*)(ab + stofs[2*i+1]) = make_ulonglong2(hp[2][i], hp[3][i]);
                }
                __syncwarp();
            }

            fwd8<false>(w2c, ab, b2v, sp2, t, stofs, w5v, dbuf);  // h1 -> h2
            fwd8<false>(w3c, ab, b3v, sp3, t, stofs, w5v, dbuf);  // h2 -> h3
            fwd8<true >(w4c, ab, b4v, sp3 /*unused*/, t, stofs, w5v, dbuf); // seed d_a4

            float accf[8][4];
            // d_a3 = (d_a4 @ W4^T) * silu'(a3)
            bwd8(w4c, (const char*)dbuf, t, t7, accf);
#pragma unroll
            for (int s = 0; s < 8; s++) {
                st4(dbuf + s * HDIM + 4 * t,
                    make_float4(accf[s][0] * sp3[0 * 8 + s],
                                accf[s][1] * sp3[1 * 8 + s],
                                accf[s][2] * sp3[2 * 8 + s],
                                accf[s][3] * sp3[3 * 8 + s]));
            }
            __syncwarp();
            // d_a2 = (d_a3 @ W3^T) * silu'(a2)
            bwd8(w3c, (const char*)dbuf, t, t7, accf);
#pragma unroll
            for (int s = 0; s < 8; s++) {
                st4(dbuf + s * HDIM + 4 * t,
                    make_float4(accf[s][0] * sp2[0 * 8 + s],
                                accf[s][1] * sp2[1 * 8 + s],
                                accf[s][2] * sp2[2 * 8 + s],
                                accf[s][3] * sp2[3 * 8 + s]));
            }
            __syncwarp();
            // d_a1 = (d_a2 @ W2^T) * silu'(a1) ; dx = d_a1 @ W1^T
            bwd8(w2c, (const char*)dbuf, t, t7, accf);

            float pdx[8][2];
#pragma unroll
            for (int s = 0; s < 8; s++) {
                float d0 = accf[s][0] * sp1[0 * 8 + s];
                float d1 = accf[s][1] * sp1[1 * 8 + s];
                float d2 = accf[s][2] * sp1[2 * 8 + s];
                float d3 = accf[s][3] * sp1[3 * 8 + s];
                pdx[s][0] = fmaf(d0, w1A[0], fmaf(d1, w1A[1],
                            fmaf(d2, w1A[2], d3 * w1A[3])));
                pdx[s][1] = fmaf(d0, w1B[0], fmaf(d1, w1B[1],
                            fmaf(d2, w1B[2], d3 * w1B[3])));
            }
            // butterfly reduce -> every lane holds full dx for all 8 samples
#pragma unroll
            for (int off = 16; off > 0; off >>= 1) {
#pragma unroll
                for (int s = 0; s < 8; s++) {
                    pdx[s][0] += __shfl_xor_sync(0xffffffffu, pdx[s][0], off);
                    pdx[s][1] += __shfl_xor_sync(0xffffffffu, pdx[s][1], off);
                }
            }

            // ---- Langevin update (replicated identically in all lanes) ----
            float fi  = (float)step;
            float eps = 10.0f * (1.0f - fi / 60.0f);
            float sq  = sqrtf(2.0f * eps);
            const float4* nzp = (const float4*)(noise + ((size_t)step * NCH + base) * 2);
            float4 n0 = nzp[0], n1 = nzp[1], n2 = nzp[2], n3 = nzp[3];
            float nzv[16] = {n0.x, n0.y, n0.z, n0.w, n1.x, n1.y, n1.z, n1.w,
                             n2.x, n2.y, n2.z, n2.w, n3.x, n3.y, n3.z, n3.w};
#pragma unroll
            for (int s = 0; s < 8; s++) {
#pragma unroll
                for (int c = 0; c < 2; c++) {
                    float nz = nzv[2 * s + c];
                    float g  = fminf(fmaxf(pdx[s][c], -0.03f), 0.03f);
                    float xv = xs[s][c] + sq * nz * 0.005f + eps * g;
                    xs[s][c] = fminf(fmaxf(xv, -2.43f), 3.05f);
                }
            }
            // next L1 store is safe: bwd8 already syncwarp'd after its reads
        }

        if (t < 16) {
            out[base * 2 + t] = xs[t >> 1][t & 1];
        }
    }
}

extern "C" void kernel_launch(void* const* d_in, const int* in_sizes, int n_in,
                              void* d_out, int out_size)
{
    const float* x0    = (const float*)d_in[0];
    const float* w1    = (const float*)d_in[1];
    const float* b1    = (const float*)d_in[2];
    const float* w2    = (const float*)d_in[3];
    const float* b2    = (const float*)d_in[4];
    const float* w3    = (const float*)d_in[5];
    const float* b3    = (const float*)d_in[6];
    const float* w4    = (const float*)d_in[7];
    const float* b4    = (const float*)d_in[8];
    const float* w5    = (const float*)d_in[9];
    const float* b5    = (const float*)d_in[10];
    const float* noise = (const float*)d_in[11];

    const int smemBytes = 57344 * (int)sizeof(float);   // 229376
    cudaFuncSetAttribute(ebm_langevin_kernel,
                         cudaFuncAttributeMaxDynamicSharedMemorySize, smemBytes);

    int nsm = 148;
    cudaDeviceGetAttribute(&nsm, cudaDevAttrMultiProcessorCount, 0);

    ebm_langevin_kernel<<<nsm, 256, smemBytes>>>(
        x0, w1, b1, w2, b2, w3, b3, w4, b4, w5, b5, noise, (float*)d_out);
}